// round 12
// baseline (speedup 1.0000x reference)
#include <cuda_runtime.h>
#include <cuda_fp16.h>
#include <cstdint>

// Problem constants
#define H 512
#define W 512
#define NDET 512
#define NSAMP 512
#define NCH 32          // B*C = 4*8
#define HW (H * W)

// Duplicated pixel-pair, channel-interleaved fp16 volume.
// Line for (y, xp) = 128 bytes = 32 x half2 { v(y,xp,c), v(y,xp+1,c) }.
__device__ static __half2 g_xt[HW * NCH];

// ---------------------------------------------------------------------------
// Pack kernel: (B,C,H,W) fp32 -> duplicated-pair interleaved fp16 lines.
// ---------------------------------------------------------------------------
__global__ void pack_kernel(const float* __restrict__ in) {
    __shared__ __half sh[130][NCH + 1];
    const int tid = threadIdx.x;
    const int seg = blockIdx.x;           // 0..3
    const int y   = blockIdx.y;           // 0..511
    const int X0  = seg * 128;

    for (int c = 0; c < NCH; ++c) {
        if (tid < 130) {
            int px = X0 + tid;
            float v = (px < W) ? in[c * HW + y * W + px] : 0.0f;
            sh[tid][c] = __float2half(v);
        }
    }
    __syncthreads();

    int4* __restrict__ gout = reinterpret_cast<int4*>(g_xt);
#pragma unroll
    for (int k = 0; k < 4; ++k) {
        int id  = tid + k * 256;
        int ll  = id >> 3;
        int jj  = id & 7;
        union { __half2 h[4]; int4 v; } u;
#pragma unroll
        for (int q = 0; q < 4; ++q)
            u.h[q] = __halves2half2(sh[ll][4 * jj + q], sh[ll + 1][4 * jj + q]);
        gout[(size_t)(y * W + X0 + ll) * 8 + jj] = u.v;
    }
}

// Exact in-loop validity predicate (must match loop arithmetic bit-for-bit).
__device__ __forceinline__ bool valid_s(int s, float nsn, float cs,
                                        float xt0, float yt0) {
    float sv = (float)s - 255.5f;
    float xs = fmaf(sv, nsn, xt0);
    float ys = fmaf(sv, cs, yt0);
    int x0 = __float2int_rd(xs);
    int y0 = __float2int_rd(ys);
    return ((unsigned)x0 <= (unsigned)(W - 2)) &
           ((unsigned)y0 <= (unsigned)(H - 2));
}

// ---------------------------------------------------------------------------
// Radon forward projection — software-pipelined.
// Warp = one (angle, detector) ray. lane = g*8+li; group g handles samples
// s ≡ g (mod 4); lane li owns channels 4li..4li+3 (one int4 per row-line).
// Valid-s interval once per ray (monotonicity => interior needs no clamp).
// Steady state: prep(sample i+1) issues its 2 LDG.128 BEFORE consume(sample i),
// guaranteeing a >= ~24-instruction load->use distance.
// ---------------------------------------------------------------------------
__global__ __launch_bounds__(256, 6) void radon_kernel(
    const float* __restrict__ angles, float* __restrict__ out, int A)
{
    const int a    = blockIdx.y;
    const int warp = threadIdx.x >> 5;
    const int lane = threadIdx.x & 31;
    const int t    = blockIdx.x * 8 + warp;     // detector index

    float ang = angles[a];
    float sn, cs;
    sincosf(ang, &sn, &cs);

    const float tv  = (float)t - 255.5f;
    const float xt0 = fmaf(tv, cs, 255.5f);
    const float yt0 = fmaf(tv, sn, 255.5f);
    const float nsn = -sn;

    // ---- valid s-interval for this ray (warp-uniform) ----
    float lo = -1e9f, hi = 1e9f;
    if (nsn > 0.f)      { lo = fmaxf(lo, (0.f   - xt0) / nsn);
                          hi = fminf(hi, (511.f - xt0) / nsn); }
    else if (nsn < 0.f) { lo = fmaxf(lo, (511.f - xt0) / nsn);
                          hi = fminf(hi, (0.f   - xt0) / nsn); }
    else if (!(xt0 >= 0.f && xt0 < 511.f)) { lo = 1.f; hi = 0.f; }
    if (cs > 0.f)       { lo = fmaxf(lo, (0.f   - yt0) / cs);
                          hi = fminf(hi, (511.f - yt0) / cs); }
    else if (cs < 0.f)  { lo = fmaxf(lo, (511.f - yt0) / cs);
                          hi = fminf(hi, (0.f   - yt0) / cs); }
    else if (!(yt0 >= 0.f && yt0 < 511.f)) { lo = 1.f; hi = 0.f; }

    lo = fmaxf(lo, -300.f);  hi = fminf(hi, 300.f);
    int s_lo = max(0,   (int)floorf(lo + 255.5f) - 2);
    int s_hi = min(511, (int)ceilf (hi + 255.5f) + 2);
    // exact fix-up against the in-loop predicate; monotone coords =>
    // every interior s is then valid (no per-sample clamp needed).
    while (s_lo <= s_hi && !valid_s(s_lo, nsn, cs, xt0, yt0)) ++s_lo;
    while (s_lo <= s_hi && !valid_s(s_hi, nsn, cs, xt0, yt0)) --s_hi;

    const int g  = lane >> 3;
    const int li = lane & 7;
    const int4* __restrict__ base = reinterpret_cast<const int4*>(g_xt) + li;

    // packed (left, right) fp32 accumulators per channel
    unsigned long long ap0 = 0ull, ap1 = 0ull, ap2 = 0ull, ap3 = 0ull;

    int s0 = s_lo + ((g - s_lo) & 3);   // first s >= s_lo with s == g (mod 4)

    // prep: compute weights + issue the two line loads for sample at sv
    auto prep = [&](float svv, int4& rA, int4& rB,
                    unsigned long long& w64, __half2& wy2) {
        float xs = fmaf(svv, nsn, xt0);
        float ys = fmaf(svv, cs, yt0);
        int   x0 = __float2int_rd(xs);
        int   y0 = __float2int_rd(ys);
        float wx = xs - (float)x0;
        float wy = ys - (float)y0;
        int cell = y0 * W + x0;         // guaranteed in-bounds (see above)
        const int4* p = base + cell * 8;
        rA = p[0];                      // row y   : ch 4li..4li+3, (L,R) half2
        rB = p[W * 8];                  // row y+1
        wy2 = __float2half2_rn(wy);
        float omx = 1.0f - wx;
        asm("mov.b64 %0, {%1, %2};" : "=l"(w64) : "f"(omx), "f"(wx));
    };

    // consume: y-lerp in fp16 SIMD, x-lerp via packed fma.rn.f32x2
    auto consume = [&](const int4& rA, const int4& rB,
                       unsigned long long w64, __half2 wy2) {
        const __half2* hA = reinterpret_cast<const __half2*>(&rA);
        const __half2* hB = reinterpret_cast<const __half2*>(&rB);
        __half2 d, ri;
        float2 f;
        unsigned long long v64;

        d = __hsub2(hB[0], hA[0]); ri = __hfma2(d, wy2, hA[0]);
        f = __half22float2(ri);
        asm("mov.b64 %0, {%1, %2};" : "=l"(v64) : "f"(f.x), "f"(f.y));
        asm("fma.rn.f32x2 %0, %1, %2, %0;" : "+l"(ap0) : "l"(v64), "l"(w64));

        d = __hsub2(hB[1], hA[1]); ri = __hfma2(d, wy2, hA[1]);
        f = __half22float2(ri);
        asm("mov.b64 %0, {%1, %2};" : "=l"(v64) : "f"(f.x), "f"(f.y));
        asm("fma.rn.f32x2 %0, %1, %2, %0;" : "+l"(ap1) : "l"(v64), "l"(w64));

        d = __hsub2(hB[2], hA[2]); ri = __hfma2(d, wy2, hA[2]);
        f = __half22float2(ri);
        asm("mov.b64 %0, {%1, %2};" : "=l"(v64) : "f"(f.x), "f"(f.y));
        asm("fma.rn.f32x2 %0, %1, %2, %0;" : "+l"(ap2) : "l"(v64), "l"(w64));

        d = __hsub2(hB[3], hA[3]); ri = __hfma2(d, wy2, hA[3]);
        f = __half22float2(ri);
        asm("mov.b64 %0, {%1, %2};" : "=l"(v64) : "f"(f.x), "f"(f.y));
        asm("fma.rn.f32x2 %0, %1, %2, %0;" : "+l"(ap3) : "l"(v64), "l"(w64));
    };

    if (s0 <= s_hi) {
        float sv = (float)s0 - 255.5f;  // exact; sv += 4.0f stays exact

        int4 rA_p, rB_p;
        unsigned long long w_p;
        __half2 wy_p;
        prep(sv, rA_p, rB_p, w_p, wy_p);

#pragma unroll 2
        for (int s = s0 + 4; s <= s_hi; s += 4) {
            sv += 4.0f;
            int4 rA_n, rB_n;
            unsigned long long w_n;
            __half2 wy_n;
            prep(sv, rA_n, rB_n, w_n, wy_n);       // loads for next sample
            consume(rA_p, rB_p, w_p, wy_p);        // consume current sample
            rA_p = rA_n; rB_p = rB_n; w_p = w_n; wy_p = wy_n;
        }
        consume(rA_p, rB_p, w_p, wy_p);
    }

    // unpack packed (L,R) accumulators and combine
    float aL, aR;
    float acc0, acc1, acc2, acc3;
    asm("mov.b64 {%0, %1}, %2;" : "=f"(aL), "=f"(aR) : "l"(ap0)); acc0 = aL + aR;
    asm("mov.b64 {%0, %1}, %2;" : "=f"(aL), "=f"(aR) : "l"(ap1)); acc1 = aL + aR;
    asm("mov.b64 {%0, %1}, %2;" : "=f"(aL), "=f"(aR) : "l"(ap2)); acc2 = aL + aR;
    asm("mov.b64 {%0, %1}, %2;" : "=f"(aL), "=f"(aR) : "l"(ap3)); acc3 = aL + aR;

    // Reduce the 4 s-phase groups (lane bits 3,4)
#pragma unroll
    for (int m_ = 8; m_ <= 16; m_ <<= 1) {
        acc0 += __shfl_xor_sync(0xffffffffu, acc0, m_);
        acc1 += __shfl_xor_sync(0xffffffffu, acc1, m_);
        acc2 += __shfl_xor_sync(0xffffffffu, acc2, m_);
        acc3 += __shfl_xor_sync(0xffffffffu, acc3, m_);
    }

    // Lane (g, li) writes channel c = 4*li + g.
    float v = (g == 0) ? acc0 : (g == 1) ? acc1 : (g == 2) ? acc2 : acc3;
    int c = 4 * li + g;
    out[(size_t)c * A * NDET + (size_t)a * NDET + t] = v;
}

extern "C" void kernel_launch(void* const* d_in, const int* in_sizes, int n_in,
                              void* d_out, int out_size)
{
    const float* x      = (const float*)d_in[0];   // (4,8,512,512) f32
    const float* angles = (const float*)d_in[1];   // (A,) f32
    float* out          = (float*)d_out;           // (4,8,A,512) f32
    const int A = in_sizes[1];

    dim3 pgrid(4, H);
    pack_kernel<<<pgrid, 256>>>(x);

    dim3 grid(NDET / 8, A);
    radon_kernel<<<grid, 256>>>(angles, out, A);
}

// round 13
// speedup vs baseline: 1.1352x; 1.1352x over previous
#include <cuda_runtime.h>
#include <cuda_fp16.h>
#include <cstdint>

// Problem constants
#define H 512
#define W 512
#define NDET 512
#define NSAMP 512
#define NCH 32          // B*C = 4*8
#define HW (H * W)

// Duplicated pixel-pair, channel-interleaved fp16 volume.
// Line for (y, xp) = 128 bytes = 32 x half2 { v(y,xp,c), v(y,xp+1,c) }.
__device__ static __half2 g_xt[HW * NCH];

// ---------------------------------------------------------------------------
// Pack kernel: (B,C,H,W) fp32 -> duplicated-pair interleaved fp16 lines.
// ---------------------------------------------------------------------------
__global__ void pack_kernel(const float* __restrict__ in) {
    __shared__ __half sh[130][NCH + 1];
    const int tid = threadIdx.x;
    const int seg = blockIdx.x;           // 0..3
    const int y   = blockIdx.y;           // 0..511
    const int X0  = seg * 128;

    for (int c = 0; c < NCH; ++c) {
        if (tid < 130) {
            int px = X0 + tid;
            float v = (px < W) ? in[c * HW + y * W + px] : 0.0f;
            sh[tid][c] = __float2half(v);
        }
    }
    __syncthreads();

    int4* __restrict__ gout = reinterpret_cast<int4*>(g_xt);
#pragma unroll
    for (int k = 0; k < 4; ++k) {
        int id  = tid + k * 256;
        int ll  = id >> 3;
        int jj  = id & 7;
        union { __half2 h[4]; int4 v; } u;
#pragma unroll
        for (int q = 0; q < 4; ++q)
            u.h[q] = __halves2half2(sh[ll][4 * jj + q], sh[ll + 1][4 * jj + q]);
        gout[(size_t)(y * W + X0 + ll) * 8 + jj] = u.v;
    }
}

// Exact in-loop validity predicate (must match loop arithmetic bit-for-bit).
__device__ __forceinline__ bool valid_s(int s, float nsn, float cs,
                                        float xt0, float yt0) {
    float sv = (float)s - 255.5f;
    float xs = fmaf(sv, nsn, xt0);
    float ys = fmaf(sv, cs, yt0);
    int x0 = __float2int_rd(xs);
    int y0 = __float2int_rd(ys);
    return ((unsigned)x0 <= (unsigned)(W - 2)) &
           ((unsigned)y0 <= (unsigned)(H - 2));
}

// ---------------------------------------------------------------------------
// Radon forward projection.
// Warp = one (angle, detector) ray. lane = g*8+li; group g handles samples
// s ≡ g (mod 4); lane li owns channels 4li..4li+3 (one int4 per row-line).
// Valid-s interval once per ray (monotonicity => interior needs no clamp).
// y-interp in fp16 SIMD (HSUB2+HFMA2); x-side deferred: separate scalar
// fp32 L/R accumulators weighted by (1-wx)/wx, combined after the loop.
// Pure-float loop counter; no packing asm (R12 spill lesson: keep state lean).
// ---------------------------------------------------------------------------
__global__ __launch_bounds__(256, 6) void radon_kernel(
    const float* __restrict__ angles, float* __restrict__ out, int A)
{
    const int a    = blockIdx.y;
    const int warp = threadIdx.x >> 5;
    const int lane = threadIdx.x & 31;
    const int t    = blockIdx.x * 8 + warp;     // detector index

    float ang = angles[a];
    float sn, cs;
    sincosf(ang, &sn, &cs);

    const float tv  = (float)t - 255.5f;
    const float xt0 = fmaf(tv, cs, 255.5f);
    const float yt0 = fmaf(tv, sn, 255.5f);
    const float nsn = -sn;

    // ---- valid s-interval for this ray (warp-uniform) ----
    float lo = -1e9f, hi = 1e9f;
    if (nsn > 0.f)      { lo = fmaxf(lo, (0.f   - xt0) / nsn);
                          hi = fminf(hi, (511.f - xt0) / nsn); }
    else if (nsn < 0.f) { lo = fmaxf(lo, (511.f - xt0) / nsn);
                          hi = fminf(hi, (0.f   - xt0) / nsn); }
    else if (!(xt0 >= 0.f && xt0 < 511.f)) { lo = 1.f; hi = 0.f; }
    if (cs > 0.f)       { lo = fmaxf(lo, (0.f   - yt0) / cs);
                          hi = fminf(hi, (511.f - yt0) / cs); }
    else if (cs < 0.f)  { lo = fmaxf(lo, (511.f - yt0) / cs);
                          hi = fminf(hi, (0.f   - yt0) / cs); }
    else if (!(yt0 >= 0.f && yt0 < 511.f)) { lo = 1.f; hi = 0.f; }

    lo = fmaxf(lo, -300.f);  hi = fminf(hi, 300.f);
    int s_lo = max(0,   (int)floorf(lo + 255.5f) - 2);
    int s_hi = min(511, (int)ceilf (hi + 255.5f) + 2);
    // exact fix-up against the in-loop predicate; monotone coords =>
    // every interior s is then valid (no per-sample clamp needed).
    while (s_lo <= s_hi && !valid_s(s_lo, nsn, cs, xt0, yt0)) ++s_lo;
    while (s_lo <= s_hi && !valid_s(s_hi, nsn, cs, xt0, yt0)) --s_hi;

    const int g  = lane >> 3;
    const int li = lane & 7;
    const int4* __restrict__ base = reinterpret_cast<const int4*>(g_xt) + li;

    // separate left/right fp32 accumulators per channel
    float aL0 = 0.f, aL1 = 0.f, aL2 = 0.f, aL3 = 0.f;
    float aR0 = 0.f, aR1 = 0.f, aR2 = 0.f, aR3 = 0.f;

    int s0 = s_lo + ((g - s_lo) & 3);   // first s >= s_lo with s == g (mod 4)
    const float sv_hi = (float)s_hi - 255.5f;   // exact

#pragma unroll 4
    for (float sv = (float)s0 - 255.5f; sv <= sv_hi; sv += 4.0f) {
        float xs = fmaf(sv, nsn, xt0);
        float ys = fmaf(sv, cs, yt0);
        int   x0 = __float2int_rd(xs);
        int   y0 = __float2int_rd(ys);
        float wx = xs - (float)x0;
        float wy = ys - (float)y0;

        int cell = (y0 << 9) + x0;      // guaranteed in-bounds (see above)

        const int4* p = base + cell * 8;
        int4 rA = p[0];                 // row y   : ch 4li..4li+3, (L,R) half2
        int4 rB = p[W * 8];             // row y+1

        __half2 wy2 = __float2half2_rn(wy);
        float omx = 1.0f - wx;

        const __half2* hA = reinterpret_cast<const __half2*>(&rA);
        const __half2* hB = reinterpret_cast<const __half2*>(&rB);

        __half2 d, ri;
        float2 f;

        d = __hsub2(hB[0], hA[0]); ri = __hfma2(d, wy2, hA[0]);
        f = __half22float2(ri);
        aL0 = fmaf(f.x, omx, aL0); aR0 = fmaf(f.y, wx, aR0);

        d = __hsub2(hB[1], hA[1]); ri = __hfma2(d, wy2, hA[1]);
        f = __half22float2(ri);
        aL1 = fmaf(f.x, omx, aL1); aR1 = fmaf(f.y, wx, aR1);

        d = __hsub2(hB[2], hA[2]); ri = __hfma2(d, wy2, hA[2]);
        f = __half22float2(ri);
        aL2 = fmaf(f.x, omx, aL2); aR2 = fmaf(f.y, wx, aR2);

        d = __hsub2(hB[3], hA[3]); ri = __hfma2(d, wy2, hA[3]);
        f = __half22float2(ri);
        aL3 = fmaf(f.x, omx, aL3); aR3 = fmaf(f.y, wx, aR3);
    }

    float acc0 = aL0 + aR0;
    float acc1 = aL1 + aR1;
    float acc2 = aL2 + aR2;
    float acc3 = aL3 + aR3;

    // Reduce the 4 s-phase groups (lane bits 3,4)
#pragma unroll
    for (int m_ = 8; m_ <= 16; m_ <<= 1) {
        acc0 += __shfl_xor_sync(0xffffffffu, acc0, m_);
        acc1 += __shfl_xor_sync(0xffffffffu, acc1, m_);
        acc2 += __shfl_xor_sync(0xffffffffu, acc2, m_);
        acc3 += __shfl_xor_sync(0xffffffffu, acc3, m_);
    }

    // Lane (g, li) writes channel c = 4*li + g.
    float v = (g == 0) ? acc0 : (g == 1) ? acc1 : (g == 2) ? acc2 : acc3;
    int c = 4 * li + g;
    out[(size_t)c * A * NDET + (size_t)a * NDET + t] = v;
}

extern "C" void kernel_launch(void* const* d_in, const int* in_sizes, int n_in,
                              void* d_out, int out_size)
{
    const float* x      = (const float*)d_in[0];   // (4,8,512,512) f32
    const float* angles = (const float*)d_in[1];   // (A,) f32
    float* out          = (float*)d_out;           // (4,8,A,512) f32
    const int A = in_sizes[1];

    dim3 pgrid(4, H);
    pack_kernel<<<pgrid, 256>>>(x);

    dim3 grid(NDET / 8, A);
    radon_kernel<<<grid, 256>>>(angles, out, A);
}

// round 14
// speedup vs baseline: 1.2868x; 1.1336x over previous
#include <cuda_runtime.h>
#include <cuda_fp16.h>
#include <cstdint>

// Problem constants
#define H 512
#define W 512
#define NDET 512
#define NSAMP 512
#define NCH 32          // B*C = 4*8
#define HW (H * W)

// Duplicated pixel-pair, channel-interleaved fp16 volume.
// Line for (y, xp) = 128 bytes = 32 x half2 { v(y,xp,c), v(y,xp+1,c) }.
__device__ static __half2 g_xt[HW * NCH];

// ---------------------------------------------------------------------------
// Pack kernel: (B,C,H,W) fp32 -> duplicated-pair interleaved fp16 lines.
// ---------------------------------------------------------------------------
__global__ void pack_kernel(const float* __restrict__ in) {
    __shared__ __half sh[130][NCH + 1];
    const int tid = threadIdx.x;
    const int seg = blockIdx.x;           // 0..3
    const int y   = blockIdx.y;           // 0..511
    const int X0  = seg * 128;

    for (int c = 0; c < NCH; ++c) {
        if (tid < 130) {
            int px = X0 + tid;
            float v = (px < W) ? in[c * HW + y * W + px] : 0.0f;
            sh[tid][c] = __float2half(v);
        }
    }
    __syncthreads();

    int4* __restrict__ gout = reinterpret_cast<int4*>(g_xt);
#pragma unroll
    for (int k = 0; k < 4; ++k) {
        int id  = tid + k * 256;
        int ll  = id >> 3;
        int jj  = id & 7;
        union { __half2 h[4]; int4 v; } u;
#pragma unroll
        for (int q = 0; q < 4; ++q)
            u.h[q] = __halves2half2(sh[ll][4 * jj + q], sh[ll + 1][4 * jj + q]);
        gout[(size_t)(y * W + X0 + ll) * 8 + jj] = u.v;
    }
}

// Exact in-loop validity predicate (must match loop arithmetic bit-for-bit).
__device__ __forceinline__ bool valid_s(int s, float nsn, float cs,
                                        float xt0, float yt0) {
    float sv = (float)s - 255.5f;
    float xs = fmaf(sv, nsn, xt0);
    float ys = fmaf(sv, cs, yt0);
    int x0 = __float2int_rd(xs);
    int y0 = __float2int_rd(ys);
    return ((unsigned)x0 <= (unsigned)(W - 2)) &
           ((unsigned)y0 <= (unsigned)(H - 2));
}

// Per-sample body: 2 LDG.128, corner weights packed to 2x half2,
// 8 HFMA2 accumulating into half2 chunk accumulators c0..c3.
#define RADON_BODY()                                                       \
    do {                                                                   \
        float xs = fmaf(sv, nsn, xt0);                                     \
        float ys = fmaf(sv, cs, yt0);                                      \
        float fx = floorf(xs);                                             \
        float fy = floorf(ys);                                             \
        float wx = xs - fx;                                                \
        float wy = ys - fy;                                                \
        int cell = (((int)fy) << 9) + (int)fx;  /* in-bounds by interval */\
        const int4* p = base + cell * 8;                                   \
        int4 rA = p[0];                                                    \
        int4 rB = p[W * 8];                                                \
        float omx = 1.0f - wx, omy = 1.0f - wy;                            \
        __half2 wa = __floats2half2_rn(omx * omy, wx * omy);               \
        __half2 wb = __floats2half2_rn(omx * wy,  wx * wy);                \
        const __half2* hA = reinterpret_cast<const __half2*>(&rA);         \
        const __half2* hB = reinterpret_cast<const __half2*>(&rB);         \
        c0 = __hfma2(hA[0], wa, c0); c0 = __hfma2(hB[0], wb, c0);          \
        c1 = __hfma2(hA[1], wa, c1); c1 = __hfma2(hB[1], wb, c1);          \
        c2 = __hfma2(hA[2], wa, c2); c2 = __hfma2(hB[2], wb, c2);          \
        c3 = __hfma2(hA[3], wa, c3); c3 = __hfma2(hB[3], wb, c3);          \
        sv += 4.0f;                                                        \
    } while (0)

// ---------------------------------------------------------------------------
// Radon forward projection.
// Warp = one (angle, detector) ray. lane = g*8+li; group g handles samples
// s ≡ g (mod 4); lane li owns channels 4li..4li+3 (one int4 per row-line).
// Valid-s interval once per ray (monotonicity => interior needs no clamp).
// Bilinear via fp16 corner weights: 2 HFMA2/channel/sample into half2 chunk
// accumulators; chunks of 4 samples folded into fp32 (bounds fp16 error).
// ---------------------------------------------------------------------------
__global__ __launch_bounds__(256, 6) void radon_kernel(
    const float* __restrict__ angles, float* __restrict__ out, int A)
{
    const int a    = blockIdx.y;
    const int warp = threadIdx.x >> 5;
    const int lane = threadIdx.x & 31;
    const int t    = blockIdx.x * 8 + warp;     // detector index

    float ang = angles[a];
    float sn, cs;
    sincosf(ang, &sn, &cs);

    const float tv  = (float)t - 255.5f;
    const float xt0 = fmaf(tv, cs, 255.5f);
    const float yt0 = fmaf(tv, sn, 255.5f);
    const float nsn = -sn;

    // ---- valid s-interval for this ray (warp-uniform) ----
    float lo = -1e9f, hi = 1e9f;
    if (nsn > 0.f)      { lo = fmaxf(lo, (0.f   - xt0) / nsn);
                          hi = fminf(hi, (511.f - xt0) / nsn); }
    else if (nsn < 0.f) { lo = fmaxf(lo, (511.f - xt0) / nsn);
                          hi = fminf(hi, (0.f   - xt0) / nsn); }
    else if (!(xt0 >= 0.f && xt0 < 511.f)) { lo = 1.f; hi = 0.f; }
    if (cs > 0.f)       { lo = fmaxf(lo, (0.f   - yt0) / cs);
                          hi = fminf(hi, (511.f - yt0) / cs); }
    else if (cs < 0.f)  { lo = fmaxf(lo, (511.f - yt0) / cs);
                          hi = fminf(hi, (0.f   - yt0) / cs); }
    else if (!(yt0 >= 0.f && yt0 < 511.f)) { lo = 1.f; hi = 0.f; }

    lo = fmaxf(lo, -300.f);  hi = fminf(hi, 300.f);
    int s_lo = max(0,   (int)floorf(lo + 255.5f) - 2);
    int s_hi = min(511, (int)ceilf (hi + 255.5f) + 2);
    // exact fix-up against the in-loop predicate; monotone coords =>
    // every interior s is then valid (no per-sample clamp needed).
    while (s_lo <= s_hi && !valid_s(s_lo, nsn, cs, xt0, yt0)) ++s_lo;
    while (s_lo <= s_hi && !valid_s(s_hi, nsn, cs, xt0, yt0)) --s_hi;

    const int g  = lane >> 3;
    const int li = lane & 7;
    const int4* __restrict__ base = reinterpret_cast<const int4*>(g_xt) + li;

    float acc0 = 0.f, acc1 = 0.f, acc2 = 0.f, acc3 = 0.f;

    int s0 = s_lo + ((g - s_lo) & 3);   // first s >= s_lo with s == g (mod 4)
    if (s0 <= s_hi) {
        int nIters = ((s_hi - s0) >> 2) + 1;
        float sv = (float)s0 - 255.5f;  // exact; sv += 4.0f stays exact
        const __half2 hz = __float2half2_rn(0.0f);
        float2 f;

        int i = 0;
        // main: chunks of 4 samples in fp16, folded to fp32 per chunk
        for (; i + 4 <= nIters; i += 4) {
            __half2 c0 = hz, c1 = hz, c2 = hz, c3 = hz;
            RADON_BODY();
            RADON_BODY();
            RADON_BODY();
            RADON_BODY();
            f = __half22float2(c0); acc0 += f.x + f.y;
            f = __half22float2(c1); acc1 += f.x + f.y;
            f = __half22float2(c2); acc2 += f.x + f.y;
            f = __half22float2(c3); acc3 += f.x + f.y;
        }
        // tail: single-sample chunks
        for (; i < nIters; ++i) {
            __half2 c0 = hz, c1 = hz, c2 = hz, c3 = hz;
            RADON_BODY();
            f = __half22float2(c0); acc0 += f.x + f.y;
            f = __half22float2(c1); acc1 += f.x + f.y;
            f = __half22float2(c2); acc2 += f.x + f.y;
            f = __half22float2(c3); acc3 += f.x + f.y;
        }
    }

    // Reduce the 4 s-phase groups (lane bits 3,4)
#pragma unroll
    for (int m_ = 8; m_ <= 16; m_ <<= 1) {
        acc0 += __shfl_xor_sync(0xffffffffu, acc0, m_);
        acc1 += __shfl_xor_sync(0xffffffffu, acc1, m_);
        acc2 += __shfl_xor_sync(0xffffffffu, acc2, m_);
        acc3 += __shfl_xor_sync(0xffffffffu, acc3, m_);
    }

    // Lane (g, li) writes channel c = 4*li + g.
    float v = (g == 0) ? acc0 : (g == 1) ? acc1 : (g == 2) ? acc2 : acc3;
    int c = 4 * li + g;
    out[(size_t)c * A * NDET + (size_t)a * NDET + t] = v;
}

extern "C" void kernel_launch(void* const* d_in, const int* in_sizes, int n_in,
                              void* d_out, int out_size)
{
    const float* x      = (const float*)d_in[0];   // (4,8,512,512) f32
    const float* angles = (const float*)d_in[1];   // (A,) f32
    float* out          = (float*)d_out;           // (4,8,A,512) f32
    const int A = in_sizes[1];

    dim3 pgrid(4, H);
    pack_kernel<<<pgrid, 256>>>(x);

    dim3 grid(NDET / 8, A);
    radon_kernel<<<grid, 256>>>(angles, out, A);
}

// round 15
// speedup vs baseline: 1.2946x; 1.0061x over previous
#include <cuda_runtime.h>
#include <cuda_fp16.h>
#include <cstdint>

// Problem constants
#define H 512
#define W 512
#define NDET 512
#define NSAMP 512
#define NCH 32          // B*C = 4*8
#define HW (H * W)

// Duplicated pixel-pair, channel-interleaved fp16 volume.
// Line for (y, xp) = 128 bytes = 32 x half2 { v(y,xp,c), v(y,xp+1,c) }.
__device__ static __half2 g_xt[HW * NCH];

// ---------------------------------------------------------------------------
// Pack kernel: (B,C,H,W) fp32 -> duplicated-pair interleaved fp16 lines.
// ---------------------------------------------------------------------------
__global__ void pack_kernel(const float* __restrict__ in) {
    __shared__ __half sh[130][NCH + 1];
    const int tid = threadIdx.x;
    const int seg = blockIdx.x;           // 0..3
    const int y   = blockIdx.y;           // 0..511
    const int X0  = seg * 128;

    for (int c = 0; c < NCH; ++c) {
        if (tid < 130) {
            int px = X0 + tid;
            float v = (px < W) ? in[c * HW + y * W + px] : 0.0f;
            sh[tid][c] = __float2half(v);
        }
    }
    __syncthreads();

    int4* __restrict__ gout = reinterpret_cast<int4*>(g_xt);
#pragma unroll
    for (int k = 0; k < 4; ++k) {
        int id  = tid + k * 256;
        int ll  = id >> 3;
        int jj  = id & 7;
        union { __half2 h[4]; int4 v; } u;
#pragma unroll
        for (int q = 0; q < 4; ++q)
            u.h[q] = __halves2half2(sh[ll][4 * jj + q], sh[ll + 1][4 * jj + q]);
        gout[(size_t)(y * W + X0 + ll) * 8 + jj] = u.v;
    }
}

// Exact in-loop validity predicate (must match loop arithmetic bit-for-bit).
__device__ __forceinline__ bool valid_s(int s, float nsn, float cs,
                                        float xt0, float yt0) {
    float sv = (float)s - 255.5f;
    float xs = fmaf(sv, nsn, xt0);
    float ys = fmaf(sv, cs, yt0);
    int x0 = __float2int_rd(xs);
    int y0 = __float2int_rd(ys);
    return ((unsigned)x0 <= (unsigned)(W - 2)) &
           ((unsigned)y0 <= (unsigned)(H - 2));
}

// Per-sample body: 2 LDG.128, corner weights packed to 2x half2,
// 8 HFMA2 accumulating into half2 chunk accumulators c0..c3.
// cell index computed in float (fy*512+fx exact in fp32 below 2^24).
#define RADON_BODY()                                                       \
    do {                                                                   \
        float xs = fmaf(sv, nsn, xt0);                                     \
        float ys = fmaf(sv, cs, yt0);                                      \
        float fx = floorf(xs);                                             \
        float fy = floorf(ys);                                             \
        float wx = xs - fx;                                                \
        float wy = ys - fy;                                                \
        int cell = (int)fmaf(fy, 512.0f, fx);   /* in-bounds by interval */\
        const int4* p = base + cell * 8;                                   \
        int4 rA = p[0];                                                    \
        int4 rB = p[W * 8];                                                \
        float omx = 1.0f - wx, omy = 1.0f - wy;                            \
        __half2 wa = __floats2half2_rn(omx * omy, wx * omy);               \
        __half2 wb = __floats2half2_rn(omx * wy,  wx * wy);                \
        const __half2* hA = reinterpret_cast<const __half2*>(&rA);         \
        const __half2* hB = reinterpret_cast<const __half2*>(&rB);         \
        c0 = __hfma2(hA[0], wa, c0); c0 = __hfma2(hB[0], wb, c0);          \
        c1 = __hfma2(hA[1], wa, c1); c1 = __hfma2(hB[1], wb, c1);          \
        c2 = __hfma2(hA[2], wa, c2); c2 = __hfma2(hB[2], wb, c2);          \
        c3 = __hfma2(hA[3], wa, c3); c3 = __hfma2(hB[3], wb, c3);          \
        sv += 4.0f;                                                        \
    } while (0)

#define RADON_FOLD()                                                       \
    do {                                                                   \
        float2 f;                                                          \
        f = __half22float2(c0); acc0 += f.x + f.y;                         \
        f = __half22float2(c1); acc1 += f.x + f.y;                         \
        f = __half22float2(c2); acc2 += f.x + f.y;                         \
        f = __half22float2(c3); acc3 += f.x + f.y;                         \
    } while (0)

// ---------------------------------------------------------------------------
// Radon forward projection.
// Warp = one (angle, detector) ray. lane = g*8+li; group g handles samples
// s ≡ g (mod 4); lane li owns channels 4li..4li+3 (one int4 per row-line).
// Valid-s interval once per ray (monotonicity => interior needs no clamp).
// Bilinear via fp16 corner weights: 2 HFMA2/channel/sample into half2 chunk
// accumulators; chunks of 8 samples folded into fp32 (bounds fp16 error).
// ---------------------------------------------------------------------------
__global__ __launch_bounds__(256, 6) void radon_kernel(
    const float* __restrict__ angles, float* __restrict__ out, int A)
{
    const int a    = blockIdx.y;
    const int warp = threadIdx.x >> 5;
    const int lane = threadIdx.x & 31;
    const int t    = blockIdx.x * 8 + warp;     // detector index

    float ang = angles[a];
    float sn, cs;
    sincosf(ang, &sn, &cs);

    const float tv  = (float)t - 255.5f;
    const float xt0 = fmaf(tv, cs, 255.5f);
    const float yt0 = fmaf(tv, sn, 255.5f);
    const float nsn = -sn;

    // ---- valid s-interval for this ray (warp-uniform) ----
    float lo = -1e9f, hi = 1e9f;
    if (nsn > 0.f)      { lo = fmaxf(lo, (0.f   - xt0) / nsn);
                          hi = fminf(hi, (511.f - xt0) / nsn); }
    else if (nsn < 0.f) { lo = fmaxf(lo, (511.f - xt0) / nsn);
                          hi = fminf(hi, (0.f   - xt0) / nsn); }
    else if (!(xt0 >= 0.f && xt0 < 511.f)) { lo = 1.f; hi = 0.f; }
    if (cs > 0.f)       { lo = fmaxf(lo, (0.f   - yt0) / cs);
                          hi = fminf(hi, (511.f - yt0) / cs); }
    else if (cs < 0.f)  { lo = fmaxf(lo, (511.f - yt0) / cs);
                          hi = fminf(hi, (0.f   - yt0) / cs); }
    else if (!(yt0 >= 0.f && yt0 < 511.f)) { lo = 1.f; hi = 0.f; }

    lo = fmaxf(lo, -300.f);  hi = fminf(hi, 300.f);
    int s_lo = max(0,   (int)floorf(lo + 255.5f) - 2);
    int s_hi = min(511, (int)ceilf (hi + 255.5f) + 2);
    // exact fix-up against the in-loop predicate; monotone coords =>
    // every interior s is then valid (no per-sample clamp needed).
    while (s_lo <= s_hi && !valid_s(s_lo, nsn, cs, xt0, yt0)) ++s_lo;
    while (s_lo <= s_hi && !valid_s(s_hi, nsn, cs, xt0, yt0)) --s_hi;

    const int g  = lane >> 3;
    const int li = lane & 7;
    const int4* __restrict__ base = reinterpret_cast<const int4*>(g_xt) + li;

    float acc0 = 0.f, acc1 = 0.f, acc2 = 0.f, acc3 = 0.f;

    int s0 = s_lo + ((g - s_lo) & 3);   // first s >= s_lo with s == g (mod 4)
    if (s0 <= s_hi) {
        int nIters = ((s_hi - s0) >> 2) + 1;
        float sv = (float)s0 - 255.5f;  // exact; sv += 4.0f stays exact
        const __half2 hz = __float2half2_rn(0.0f);

        int i = 0;
        // main: chunks of 8 samples in fp16, folded to fp32 per chunk
        for (; i + 8 <= nIters; i += 8) {
            __half2 c0 = hz, c1 = hz, c2 = hz, c3 = hz;
            RADON_BODY(); RADON_BODY(); RADON_BODY(); RADON_BODY();
            RADON_BODY(); RADON_BODY(); RADON_BODY(); RADON_BODY();
            RADON_FOLD();
        }
        // tail: single-sample chunks
        for (; i < nIters; ++i) {
            __half2 c0 = hz, c1 = hz, c2 = hz, c3 = hz;
            RADON_BODY();
            RADON_FOLD();
        }
    }

    // Reduce the 4 s-phase groups (lane bits 3,4)
#pragma unroll
    for (int m_ = 8; m_ <= 16; m_ <<= 1) {
        acc0 += __shfl_xor_sync(0xffffffffu, acc0, m_);
        acc1 += __shfl_xor_sync(0xffffffffu, acc1, m_);
        acc2 += __shfl_xor_sync(0xffffffffu, acc2, m_);
        acc3 += __shfl_xor_sync(0xffffffffu, acc3, m_);
    }

    // Lane (g, li) writes channel c = 4*li + g.
    float v = (g == 0) ? acc0 : (g == 1) ? acc1 : (g == 2) ? acc2 : acc3;
    int c = 4 * li + g;
    out[(size_t)c * A * NDET + (size_t)a * NDET + t] = v;
}

extern "C" void kernel_launch(void* const* d_in, const int* in_sizes, int n_in,
                              void* d_out, int out_size)
{
    const float* x      = (const float*)d_in[0];   // (4,8,512,512) f32
    const float* angles = (const float*)d_in[1];   // (A,) f32
    float* out          = (float*)d_out;           // (4,8,A,512) f32
    const int A = in_sizes[1];

    dim3 pgrid(4, H);
    pack_kernel<<<pgrid, 256>>>(x);

    dim3 grid(NDET / 8, A);
    radon_kernel<<<grid, 256>>>(angles, out, A);
}